// round 8
// baseline (speedup 1.0000x reference)
#include <cuda_runtime.h>
#include <cuda_bf16.h>
#include <cstdint>

#define NN 30000
#define EE 480000
#define HSTR 288      // hcat row stride (max K)
#define FD 256        // ft row width (H*64)

// ---------------- scratch (device globals; no allocs allowed) ----------------
__device__ float g_hcat[NN * HSTR];     // [h | pe] per layer, tf32-rounded
__device__ float g_ft[NN * FD];         // per-layer transformed features
__device__ float g_Wr[3 * 288 * 256];   // tf32-rounded weights, all layers
__device__ float g_a1[NN * 4];
__device__ float g_a2[NN * 4];
__device__ int   g_cnt[NN];
__device__ int   g_off[NN + 1];
__device__ int   g_csr_src[EE];

__device__ __forceinline__ uint32_t f2tf32(float v) {
    uint32_t t;
    asm("cvt.rna.tf32.f32 %0, %1;" : "=r"(t) : "f"(v));
    return t;
}

// ---------------- hcat assembly (tf32-rounded) ----------------
__global__ void k_copy_feat(const float* __restrict__ f) {
    int i = blockIdx.x * blockDim.x + threadIdx.x;
    if (i < NN * 128) {
        int n = i >> 7, c = i & 127;
        g_hcat[n * HSTR + c] = __uint_as_float(f2tf32(f[i]));
    }
}

__global__ void k_fill_pe(const float* __restrict__ pe, const int* __restrict__ pos, int col0) {
    int i = blockIdx.x * blockDim.x + threadIdx.x;
    if (i < NN * 32) {
        int n = i >> 5, c = i & 31;
        g_hcat[n * HSTR + col0 + c] = __uint_as_float(f2tf32(pe[pos[n] * 32 + c]));
    }
}

__global__ void k_round_all(const float* __restrict__ W0, const float* __restrict__ W1,
                            const float* __restrict__ W2) {
    int i = blockIdx.x * blockDim.x + threadIdx.x;
    const int n0 = 160 * 256, n12 = 288 * 256;
    if (i < n0)
        g_Wr[i] = __uint_as_float(f2tf32(W0[i]));
    if (i < n12) {
        g_Wr[288 * 256 + i]     = __uint_as_float(f2tf32(W1[i]));
        g_Wr[2 * 288 * 256 + i] = __uint_as_float(f2tf32(W2[i]));
    }
}

// ---------------- CSR build ----------------
__global__ void k_zero_cnt() {
    int i = blockIdx.x * blockDim.x + threadIdx.x;
    if (i < NN) g_cnt[i] = 0;
}

__global__ void k_count(const int* __restrict__ dst) {
    int e = blockIdx.x * blockDim.x + threadIdx.x;
    if (e < EE) atomicAdd(&g_cnt[dst[e]], 1);
}

__global__ void k_scan() {
    __shared__ int warp_sums[32];
    __shared__ int s_carry;
    int tid = threadIdx.x;
    int lane = tid & 31, wid = tid >> 5;
    if (tid == 0) s_carry = 0;
    __syncthreads();
    for (int base = 0; base < NN; base += 1024) {
        int i = base + tid;
        int v = (i < NN) ? g_cnt[i] : 0;
        int x = v;
        #pragma unroll
        for (int d = 1; d < 32; d <<= 1) {
            int y = __shfl_up_sync(0xffffffffu, x, d);
            if (lane >= d) x += y;
        }
        if (lane == 31) warp_sums[wid] = x;
        __syncthreads();
        if (wid == 0) {
            int s = warp_sums[lane];
            #pragma unroll
            for (int d = 1; d < 32; d <<= 1) {
                int y = __shfl_up_sync(0xffffffffu, s, d);
                if (lane >= d) s += y;
            }
            warp_sums[lane] = s;
        }
        __syncthreads();
        int carry = s_carry;
        int excl = x - v + (wid > 0 ? warp_sums[wid - 1] : 0);
        if (i < NN) {
            g_off[i] = carry + excl;
            g_cnt[i] = carry + excl;
        }
        int chunk_total = warp_sums[31];
        __syncthreads();
        if (tid == 0) s_carry = carry + chunk_total;
        __syncthreads();
    }
    if (threadIdx.x == 0) g_off[NN] = s_carry;
}

__global__ void k_place(const int* __restrict__ src, const int* __restrict__ dst) {
    int e = blockIdx.x * blockDim.x + threadIdx.x;
    if (e < EE) {
        int p = atomicAdd(&g_cnt[dst[e]], 1);
        g_csr_src[p] = src[e];
    }
}

// ---------------- TF32 GEMM: 8 warps (4M x 2N, tile 32x64), 3-stage cp.async ----------------
// BSTR=136 keeps B-frag LDS conflict-free. 64 accum regs/thread ->
// __launch_bounds__(256,2) gives 2 CTAs/SM = 16 warps/SM for latency hiding.
#define BM 128
#define BN 128
#define BK 16
#define ASTR 20
#define BSTR 136
#define ABYTES (BM * ASTR * 4)
#define BBYTES (BK * BSTR * 4)
#define GSMEM (3 * (ABYTES + BBYTES))

__device__ __forceinline__ void cpa16(uint32_t dst, const float* src, int sz) {
    asm volatile("cp.async.cg.shared.global [%0], [%1], 16, %2;\n"
                 :: "r"(dst), "l"(src), "r"(sz));
}

__global__ __launch_bounds__(256, 2) void k_gemm_tf32(const float* __restrict__ Wb, int K,
                                                      const float* __restrict__ al,
                                                      const float* __restrict__ ar) {
    extern __shared__ char smem[];
    int bm = blockIdx.y * BM;
    int bn = blockIdx.x * BN;
    int tid = threadIdx.x;
    int lane = tid & 31, warp = tid >> 5;
    int warpM = warp & 3, warpN = warp >> 2;     // 4 x 2
    int gid = lane >> 2, tig = lane & 3;

    float c[2][8][4] = {};

    // per-thread cp.async chunk lists: 2 A chunks + 2 B chunks (16B each)
    int arow[2], akq[2], apred[2];
    const float* asrc[2];
    uint32_t adst[2];
    int bkk[2], bnq[2];
    const float* bsrc[2];
    uint32_t bdst[2];
    uint32_t sbase = (uint32_t)__cvta_generic_to_shared(smem);
    #pragma unroll
    for (int j = 0; j < 2; j++) {
        int ch = tid + j * 256;
        arow[j] = ch >> 2; akq[j] = (ch & 3) * 4;
        apred[j] = (bm + arow[j]) < NN ? 16 : 0;
        asrc[j] = g_hcat + (size_t)(apred[j] ? bm + arow[j] : 0) * HSTR + akq[j];
        adst[j] = sbase + (arow[j] * ASTR + akq[j]) * 4;
        bkk[j] = ch >> 5; bnq[j] = (ch & 31) * 4;
        bsrc[j] = Wb + bkk[j] * 256 + bn + bnq[j];
        bdst[j] = sbase + 3 * ABYTES + (bkk[j] * BSTR + bnq[j]) * 4;
    }

    int T = K / BK;

    // prologue: tiles 0 and 1
    #pragma unroll
    for (int j = 0; j < 2; j++) cpa16(adst[j], asrc[j], apred[j]);
    #pragma unroll
    for (int j = 0; j < 2; j++) cpa16(bdst[j], bsrc[j], 16);
    asm volatile("cp.async.commit_group;\n");
    if (T > 1) {
        #pragma unroll
        for (int j = 0; j < 2; j++) cpa16(adst[j] + ABYTES, asrc[j] + BK, apred[j]);
        #pragma unroll
        for (int j = 0; j < 2; j++) cpa16(bdst[j] + BBYTES, bsrc[j] + BK * 256, 16);
        asm volatile("cp.async.commit_group;\n");
    }

    for (int t = 0; t < T; t++) {
        if (t + 1 < T)
            asm volatile("cp.async.wait_group 1;\n");
        else
            asm volatile("cp.async.wait_group 0;\n");
        __syncthreads();

        if (t + 2 < T) {
            int st = (t + 2) % 3;
            int k0 = (t + 2) * BK;
            #pragma unroll
            for (int j = 0; j < 2; j++) cpa16(adst[j] + st * ABYTES, asrc[j] + k0, apred[j]);
            #pragma unroll
            for (int j = 0; j < 2; j++) cpa16(bdst[j] + st * BBYTES, bsrc[j] + k0 * 256, 16);
            asm volatile("cp.async.commit_group;\n");
        }

        const float* Ac = (const float*)(smem + (t % 3) * ABYTES);
        const float* Bc = (const float*)(smem + 3 * ABYTES + (t % 3) * BBYTES);
        #pragma unroll
        for (int ks = 0; ks < BK; ks += 8) {
            uint32_t a[2][4], b[8][2];
            #pragma unroll
            for (int mt = 0; mt < 2; mt++) {
                int m0 = warpM * 32 + mt * 16 + gid;
                a[mt][0] = __float_as_uint(Ac[m0 * ASTR + ks + tig]);
                a[mt][1] = __float_as_uint(Ac[(m0 + 8) * ASTR + ks + tig]);
                a[mt][2] = __float_as_uint(Ac[m0 * ASTR + ks + tig + 4]);
                a[mt][3] = __float_as_uint(Ac[(m0 + 8) * ASTR + ks + tig + 4]);
            }
            #pragma unroll
            for (int nt = 0; nt < 8; nt++) {
                int n0 = warpN * 64 + nt * 8 + gid;
                b[nt][0] = __float_as_uint(Bc[(ks + tig) * BSTR + n0]);
                b[nt][1] = __float_as_uint(Bc[(ks + tig + 4) * BSTR + n0]);
            }
            #pragma unroll
            for (int mt = 0; mt < 2; mt++)
                #pragma unroll
                for (int nt = 0; nt < 8; nt++)
                    asm volatile(
                        "mma.sync.aligned.m16n8k8.row.col.f32.tf32.tf32.f32 "
                        "{%0,%1,%2,%3}, {%4,%5,%6,%7}, {%8,%9}, {%0,%1,%2,%3};"
                        : "+f"(c[mt][nt][0]), "+f"(c[mt][nt][1]),
                          "+f"(c[mt][nt][2]), "+f"(c[mt][nt][3])
                        : "r"(a[mt][0]), "r"(a[mt][1]), "r"(a[mt][2]), "r"(a[mt][3]),
                          "r"(b[nt][0]), "r"(b[nt][1]));
        }
        __syncthreads();
    }

    // epilogue: store ft + fused a1/a2 row-dots (warp tile = one head's 64 cols)
    int h = blockIdx.x * 2 + warpN;
    const float* alh = al + h * 64;
    const float* arh = ar + h * 64;
    float lw[8][2], rw[8][2];
    #pragma unroll
    for (int nt = 0; nt < 8; nt++) {
        int c64 = nt * 8 + tig * 2;
        lw[nt][0] = alh[c64]; lw[nt][1] = alh[c64 + 1];
        rw[nt][0] = arh[c64]; rw[nt][1] = arh[c64 + 1];
    }
    #pragma unroll
    for (int mt = 0; mt < 2; mt++) {
        int row0 = bm + warpM * 32 + mt * 16 + gid;
        int row1 = row0 + 8;
        float s1r0 = 0.f, s2r0 = 0.f, s1r1 = 0.f, s2r1 = 0.f;
        #pragma unroll
        for (int nt = 0; nt < 8; nt++) {
            int col = bn + warpN * 64 + nt * 8 + tig * 2;
            s1r0 += c[mt][nt][0] * lw[nt][0] + c[mt][nt][1] * lw[nt][1];
            s2r0 += c[mt][nt][0] * rw[nt][0] + c[mt][nt][1] * rw[nt][1];
            s1r1 += c[mt][nt][2] * lw[nt][0] + c[mt][nt][3] * lw[nt][1];
            s2r1 += c[mt][nt][2] * rw[nt][0] + c[mt][nt][3] * rw[nt][1];
            if (row0 < NN)
                *(float2*)(g_ft + row0 * FD + col) = make_float2(c[mt][nt][0], c[mt][nt][1]);
            if (row1 < NN)
                *(float2*)(g_ft + row1 * FD + col) = make_float2(c[mt][nt][2], c[mt][nt][3]);
        }
        #pragma unroll
        for (int d = 1; d < 4; d <<= 1) {
            s1r0 += __shfl_xor_sync(0xffffffffu, s1r0, d);
            s2r0 += __shfl_xor_sync(0xffffffffu, s2r0, d);
            s1r1 += __shfl_xor_sync(0xffffffffu, s1r1, d);
            s2r1 += __shfl_xor_sync(0xffffffffu, s2r1, d);
        }
        if (tig == 0) {
            if (row0 < NN) { g_a1[row0 * 4 + h] = s1r0; g_a2[row0 * 4 + h] = s2r0; }
            if (row1 < NN) { g_a1[row1 * 4 + h] = s1r1; g_a2[row1 * 4 + h] = s2r1; }
        }
    }
}

// ---------------- edge phase: single-pass online softmax, one warp per dst ----------------
__global__ void k_edge(float* __restrict__ out, int final_layer,
                       const float* __restrict__ pe_next, const int* __restrict__ pos) {
    int gw = (blockIdx.x * blockDim.x + threadIdx.x) >> 5;
    int lane = threadIdx.x & 31;
    if (gw >= NN) return;
    int n = gw;
    int h = lane >> 3;
    float a2h = g_a2[n * 4 + h];
    int beg = g_off[n], end = g_off[n + 1];

    float m = -1e30f, ssum = 0.f;
    float acc[8] = {0, 0, 0, 0, 0, 0, 0, 0};

    if (beg < end) {
        int s = g_csr_src[beg];
        float a1v = g_a1[s * 4 + h];
        for (int i = beg; i < end; i++) {
            int s_nxt = 0; float a1_nxt = 0.f;
            if (i + 1 < end) {
                s_nxt = g_csr_src[i + 1];
                a1_nxt = g_a1[s_nxt * 4 + h];
            }
            float e = a1v + a2h;
            e = e > 0.f ? e : 0.2f * e;
            float mn = fmaxf(m, e);
            float sc = __expf(m - mn);
            float f = __expf(e - mn);
            ssum = ssum * sc + f;
            m = mn;
            const float4* p = (const float4*)(g_ft + (size_t)s * FD + lane * 8);
            float4 u = p[0], ww = p[1];
            acc[0] = acc[0] * sc + u.x * f;  acc[1] = acc[1] * sc + u.y * f;
            acc[2] = acc[2] * sc + u.z * f;  acc[3] = acc[3] * sc + u.w * f;
            acc[4] = acc[4] * sc + ww.x * f; acc[5] = acc[5] * sc + ww.y * f;
            acc[6] = acc[6] * sc + ww.z * f; acc[7] = acc[7] * sc + ww.w * f;
            s = s_nxt; a1v = a1_nxt;
        }
    }
    float inv = ssum > 0.f ? 1.0f / ssum : 0.f;
    #pragma unroll
    for (int j = 0; j < 8; j++) acc[j] *= inv;

    if (final_layer) {
        #pragma unroll
        for (int j = 0; j < 8; j++) {
            acc[j] += __shfl_xor_sync(0xffffffffu, acc[j], 8);
            acc[j] += __shfl_xor_sync(0xffffffffu, acc[j], 16);
        }
        if (lane < 8) {
            #pragma unroll
            for (int j = 0; j < 8; j++)
                out[n * 64 + lane * 8 + j] = acc[j] * 0.25f;
        }
    } else {
        float* d = g_hcat + n * HSTR + lane * 8;
        #pragma unroll
        for (int j = 0; j < 8; j++) {
            float x = acc[j];
            x = x > 0.f ? x : expm1f(x);              // ELU
            d[j] = __uint_as_float(f2tf32(x));        // pre-round for next GEMM
        }
        g_hcat[n * HSTR + 256 + lane] =
            __uint_as_float(f2tf32(pe_next[pos[n] * 32 + lane]));
    }
}

// ---------------- launcher ----------------
extern "C" void kernel_launch(void* const* d_in, const int* in_sizes, int n_in,
                              void* d_out, int out_size) {
    const float* features = (const float*)d_in[0];
    const float* W0  = (const float*)d_in[1];
    const float* al0 = (const float*)d_in[2];
    const float* ar0 = (const float*)d_in[3];
    const float* pe0 = (const float*)d_in[4];
    const float* W1  = (const float*)d_in[5];
    const float* al1 = (const float*)d_in[6];
    const float* ar1 = (const float*)d_in[7];
    const float* pe1 = (const float*)d_in[8];
    const float* W2  = (const float*)d_in[9];
    const float* al2 = (const float*)d_in[10];
    const float* ar2 = (const float*)d_in[11];
    const float* pe2 = (const float*)d_in[12];
    const int* src = (const int*)d_in[13];
    const int* dst = (const int*)d_in[14];
    const int* pos = (const int*)d_in[15];
    float* out = (float*)d_out;

    float* Wr0 = nullptr; cudaGetSymbolAddress((void**)&Wr0, g_Wr);
    float* Wr1 = Wr0 + 288 * 256;
    float* Wr2 = Wr0 + 2 * 288 * 256;

    cudaFuncSetAttribute(k_gemm_tf32, cudaFuncAttributeMaxDynamicSharedMemorySize, GSMEM);

    dim3 ggrid(2, (NN + BM - 1) / BM);
    int edge_blocks = (NN + 7) / 8;

    // Ordered so the GEMM is the 4th launch (ncu capture lands on it).
    k_copy_feat<<<(NN * 128 + 255) / 256, 256>>>(features);               // 1
    k_fill_pe<<<(NN * 32 + 255) / 256, 256>>>(pe0, pos, 128);             // 2
    k_round_all<<<(288 * 256 + 255) / 256, 256>>>(W0, W1, W2);            // 3
    k_gemm_tf32<<<ggrid, 256, GSMEM>>>(Wr0, 160, al0, ar0);               // 4  <- profiled

    // CSR build
    k_zero_cnt<<<(NN + 255) / 256, 256>>>();                              // 5
    k_count<<<(EE + 255) / 256, 256>>>(dst);                              // 6
    k_scan<<<1, 1024>>>();                                                // 7
    k_place<<<(EE + 255) / 256, 256>>>(src, dst);                         // 8

    k_edge<<<edge_blocks, 256>>>(out, 0, pe1, pos);                       // 9

    k_gemm_tf32<<<ggrid, 256, GSMEM>>>(Wr1, 288, al1, ar1);               // 10
    k_edge<<<edge_blocks, 256>>>(out, 0, pe2, pos);                       // 11

    k_gemm_tf32<<<ggrid, 256, GSMEM>>>(Wr2, 288, al2, ar2);               // 12
    k_edge<<<edge_blocks, 256>>>(out, 1, nullptr, nullptr);               // 13
}

// round 9
// speedup vs baseline: 1.1024x; 1.1024x over previous
#include <cuda_runtime.h>
#include <cuda_bf16.h>
#include <cuda_fp16.h>
#include <cstdint>

#define NN 30000
#define EE 480000
#define HSTR 256      // hcat row stride (= max GEMM K after pe-lookup)
#define FD 256        // ft row width (H*64)

// ---------------- scratch (device globals; no allocs allowed) ----------------
__device__ float  g_hcat[NN * HSTR];     // GEMM input rows, tf32-rounded
__device__ __half g_ft[NN * FD];         // per-layer transformed features (fp16)
__device__ float  g_Wr[3 * 288 * 256];   // tf32-rounded weights, all layers
__device__ float  g_PW[3 * 3 * 256];     // pe[p] @ W_pe per layer (pos lookup)
__device__ float  g_a1[NN * 4];
__device__ float  g_a2[NN * 4];
__device__ int    g_cnt[NN];
__device__ int    g_off[NN + 1];
__device__ int    g_csr_src[EE];

__device__ __forceinline__ uint32_t f2tf32(float v) {
    uint32_t t;
    asm("cvt.rna.tf32.f32 %0, %1;" : "=r"(t) : "f"(v));
    return t;
}

// ---------------- input prep ----------------
__global__ void k_copy_feat(const float* __restrict__ f) {
    int i = blockIdx.x * blockDim.x + threadIdx.x;
    if (i < NN * 128) {
        int n = i >> 7, c = i & 127;
        g_hcat[n * HSTR + c] = __uint_as_float(f2tf32(f[i]));
    }
}

__global__ void k_round_all(const float* __restrict__ W0, const float* __restrict__ W1,
                            const float* __restrict__ W2) {
    int i = blockIdx.x * blockDim.x + threadIdx.x;
    const int n0 = 160 * 256, n12 = 288 * 256;
    if (i < n0)
        g_Wr[i] = __uint_as_float(f2tf32(W0[i]));
    if (i < n12) {
        g_Wr[288 * 256 + i]     = __uint_as_float(f2tf32(W1[i]));
        g_Wr[2 * 288 * 256 + i] = __uint_as_float(f2tf32(W2[i]));
    }
}

// PW[l][p][c] = sum_k tf32(pe_l[p,k]) * Wr_l[K_feat + k, c]
__global__ void k_pw(const float* __restrict__ pe0, const float* __restrict__ pe1,
                     const float* __restrict__ pe2) {
    int i = blockIdx.x * blockDim.x + threadIdx.x;
    if (i >= 3 * 3 * 256) return;
    int c = i & 255, p = (i >> 8) % 3, l = i / (3 * 256);
    const float* pe = (l == 0) ? pe0 : (l == 1 ? pe1 : pe2);
    const float* Wp = (l == 0) ? (g_Wr + 128 * 256)
                               : (g_Wr + l * 288 * 256 + 256 * 256);
    float s = 0.f;
    #pragma unroll
    for (int k = 0; k < 32; k++)
        s += __uint_as_float(f2tf32(pe[p * 32 + k])) * Wp[k * 256 + c];
    g_PW[(l * 3 + p) * 256 + c] = s;
}

// ---------------- CSR build ----------------
__global__ void k_zero_cnt() {
    int i = blockIdx.x * blockDim.x + threadIdx.x;
    if (i < NN) g_cnt[i] = 0;
}

__global__ void k_count(const int* __restrict__ dst) {
    int e = blockIdx.x * blockDim.x + threadIdx.x;
    if (e < EE) atomicAdd(&g_cnt[dst[e]], 1);
}

__global__ void k_scan() {
    __shared__ int warp_sums[32];
    __shared__ int s_carry;
    int tid = threadIdx.x;
    int lane = tid & 31, wid = tid >> 5;
    if (tid == 0) s_carry = 0;
    __syncthreads();
    for (int base = 0; base < NN; base += 1024) {
        int i = base + tid;
        int v = (i < NN) ? g_cnt[i] : 0;
        int x = v;
        #pragma unroll
        for (int d = 1; d < 32; d <<= 1) {
            int y = __shfl_up_sync(0xffffffffu, x, d);
            if (lane >= d) x += y;
        }
        if (lane == 31) warp_sums[wid] = x;
        __syncthreads();
        if (wid == 0) {
            int s = warp_sums[lane];
            #pragma unroll
            for (int d = 1; d < 32; d <<= 1) {
                int y = __shfl_up_sync(0xffffffffu, s, d);
                if (lane >= d) s += y;
            }
            warp_sums[lane] = s;
        }
        __syncthreads();
        int carry = s_carry;
        int excl = x - v + (wid > 0 ? warp_sums[wid - 1] : 0);
        if (i < NN) {
            g_off[i] = carry + excl;
            g_cnt[i] = carry + excl;
        }
        int chunk_total = warp_sums[31];
        __syncthreads();
        if (tid == 0) s_carry = carry + chunk_total;
        __syncthreads();
    }
    if (threadIdx.x == 0) g_off[NN] = s_carry;
}

__global__ void k_place(const int* __restrict__ src, const int* __restrict__ dst) {
    int e = blockIdx.x * blockDim.x + threadIdx.x;
    if (e < EE) {
        int p = atomicAdd(&g_cnt[dst[e]], 1);
        g_csr_src[p] = src[e];
    }
}

// ---------------- TF32 GEMM + PW(pos) add + fused a1/a2 epilogue, fp16 ft out ----------------
#define BM 128
#define BN 128
#define BK 16
#define ASTR 20
#define BSTR 136
#define ABYTES (BM * ASTR * 4)
#define BBYTES (BK * BSTR * 4)
#define GSMEM (3 * (ABYTES + BBYTES))

__device__ __forceinline__ void cpa16(uint32_t dst, const float* src, int sz) {
    asm volatile("cp.async.cg.shared.global [%0], [%1], 16, %2;\n"
                 :: "r"(dst), "l"(src), "r"(sz));
}

__global__ __launch_bounds__(256, 2) void k_gemm_tf32(const float* __restrict__ Wb, int K,
                                                      const float* __restrict__ al,
                                                      const float* __restrict__ ar,
                                                      const float* __restrict__ PWl,
                                                      const int* __restrict__ pos) {
    extern __shared__ char smem[];
    int bm = blockIdx.y * BM;
    int bn = blockIdx.x * BN;
    int tid = threadIdx.x;
    int lane = tid & 31, warp = tid >> 5;
    int warpM = warp & 3, warpN = warp >> 2;     // 4 x 2
    int gid = lane >> 2, tig = lane & 3;

    float c[2][8][4] = {};

    int arow[2], akq[2], apred[2];
    const float* asrc[2];
    uint32_t adst[2];
    int bkk[2], bnq[2];
    const float* bsrc[2];
    uint32_t bdst[2];
    uint32_t sbase = (uint32_t)__cvta_generic_to_shared(smem);
    #pragma unroll
    for (int j = 0; j < 2; j++) {
        int ch = tid + j * 256;
        arow[j] = ch >> 2; akq[j] = (ch & 3) * 4;
        apred[j] = (bm + arow[j]) < NN ? 16 : 0;
        asrc[j] = g_hcat + (size_t)(apred[j] ? bm + arow[j] : 0) * HSTR + akq[j];
        adst[j] = sbase + (arow[j] * ASTR + akq[j]) * 4;
        bkk[j] = ch >> 5; bnq[j] = (ch & 31) * 4;
        bsrc[j] = Wb + bkk[j] * 256 + bn + bnq[j];
        bdst[j] = sbase + 3 * ABYTES + (bkk[j] * BSTR + bnq[j]) * 4;
    }

    int T = K / BK;

    #pragma unroll
    for (int j = 0; j < 2; j++) cpa16(adst[j], asrc[j], apred[j]);
    #pragma unroll
    for (int j = 0; j < 2; j++) cpa16(bdst[j], bsrc[j], 16);
    asm volatile("cp.async.commit_group;\n");
    if (T > 1) {
        #pragma unroll
        for (int j = 0; j < 2; j++) cpa16(adst[j] + ABYTES, asrc[j] + BK, apred[j]);
        #pragma unroll
        for (int j = 0; j < 2; j++) cpa16(bdst[j] + BBYTES, bsrc[j] + BK * 256, 16);
        asm volatile("cp.async.commit_group;\n");
    }

    for (int t = 0; t < T; t++) {
        if (t + 1 < T)
            asm volatile("cp.async.wait_group 1;\n");
        else
            asm volatile("cp.async.wait_group 0;\n");
        __syncthreads();

        if (t + 2 < T) {
            int st = (t + 2) % 3;
            int k0 = (t + 2) * BK;
            #pragma unroll
            for (int j = 0; j < 2; j++) cpa16(adst[j] + st * ABYTES, asrc[j] + k0, apred[j]);
            #pragma unroll
            for (int j = 0; j < 2; j++) cpa16(bdst[j] + st * BBYTES, bsrc[j] + k0 * 256, 16);
            asm volatile("cp.async.commit_group;\n");
        }

        const float* Ac = (const float*)(smem + (t % 3) * ABYTES);
        const float* Bc = (const float*)(smem + 3 * ABYTES + (t % 3) * BBYTES);
        #pragma unroll
        for (int ks = 0; ks < BK; ks += 8) {
            uint32_t a[2][4], b[8][2];
            #pragma unroll
            for (int mt = 0; mt < 2; mt++) {
                int m0 = warpM * 32 + mt * 16 + gid;
                a[mt][0] = __float_as_uint(Ac[m0 * ASTR + ks + tig]);
                a[mt][1] = __float_as_uint(Ac[(m0 + 8) * ASTR + ks + tig]);
                a[mt][2] = __float_as_uint(Ac[m0 * ASTR + ks + tig + 4]);
                a[mt][3] = __float_as_uint(Ac[(m0 + 8) * ASTR + ks + tig + 4]);
            }
            #pragma unroll
            for (int nt = 0; nt < 8; nt++) {
                int n0 = warpN * 64 + nt * 8 + gid;
                b[nt][0] = __float_as_uint(Bc[(ks + tig) * BSTR + n0]);
                b[nt][1] = __float_as_uint(Bc[(ks + tig + 4) * BSTR + n0]);
            }
            #pragma unroll
            for (int mt = 0; mt < 2; mt++)
                #pragma unroll
                for (int nt = 0; nt < 8; nt++)
                    asm volatile(
                        "mma.sync.aligned.m16n8k8.row.col.f32.tf32.tf32.f32 "
                        "{%0,%1,%2,%3}, {%4,%5,%6,%7}, {%8,%9}, {%0,%1,%2,%3};"
                        : "+f"(c[mt][nt][0]), "+f"(c[mt][nt][1]),
                          "+f"(c[mt][nt][2]), "+f"(c[mt][nt][3])
                        : "r"(a[mt][0]), "r"(a[mt][1]), "r"(a[mt][2]), "r"(a[mt][3]),
                          "r"(b[nt][0]), "r"(b[nt][1]));
        }
        __syncthreads();
    }

    // epilogue: += PW[pos[row]], store ft (fp16), fused a1/a2 row-dots
    int h = blockIdx.x * 2 + warpN;
    const float* alh = al + h * 64;
    const float* arh = ar + h * 64;
    float lw[8][2], rw[8][2];
    #pragma unroll
    for (int nt = 0; nt < 8; nt++) {
        int c64 = nt * 8 + tig * 2;
        lw[nt][0] = alh[c64]; lw[nt][1] = alh[c64 + 1];
        rw[nt][0] = arh[c64]; rw[nt][1] = arh[c64 + 1];
    }
    #pragma unroll
    for (int mt = 0; mt < 2; mt++) {
        int row0 = bm + warpM * 32 + mt * 16 + gid;
        int row1 = row0 + 8;
        const float* pw0 = PWl + (row0 < NN ? pos[row0] : 0) * 256;
        const float* pw1 = PWl + (row1 < NN ? pos[row1] : 0) * 256;
        float s1r0 = 0.f, s2r0 = 0.f, s1r1 = 0.f, s2r1 = 0.f;
        #pragma unroll
        for (int nt = 0; nt < 8; nt++) {
            int col = bn + warpN * 64 + nt * 8 + tig * 2;
            float v00 = c[mt][nt][0] + pw0[col], v01 = c[mt][nt][1] + pw0[col + 1];
            float v10 = c[mt][nt][2] + pw1[col], v11 = c[mt][nt][3] + pw1[col + 1];
            s1r0 += v00 * lw[nt][0] + v01 * lw[nt][1];
            s2r0 += v00 * rw[nt][0] + v01 * rw[nt][1];
            s1r1 += v10 * lw[nt][0] + v11 * lw[nt][1];
            s2r1 += v10 * rw[nt][0] + v11 * rw[nt][1];
            if (row0 < NN)
                *(half2*)(g_ft + (size_t)row0 * FD + col) = __floats2half2_rn(v00, v01);
            if (row1 < NN)
                *(half2*)(g_ft + (size_t)row1 * FD + col) = __floats2half2_rn(v10, v11);
        }
        #pragma unroll
        for (int d = 1; d < 4; d <<= 1) {
            s1r0 += __shfl_xor_sync(0xffffffffu, s1r0, d);
            s2r0 += __shfl_xor_sync(0xffffffffu, s2r0, d);
            s1r1 += __shfl_xor_sync(0xffffffffu, s1r1, d);
            s2r1 += __shfl_xor_sync(0xffffffffu, s2r1, d);
        }
        if (tig == 0) {
            if (row0 < NN) { g_a1[row0 * 4 + h] = s1r0; g_a2[row0 * 4 + h] = s2r0; }
            if (row1 < NN) { g_a1[row1 * 4 + h] = s1r1; g_a2[row1 * 4 + h] = s2r1; }
        }
    }
}

// ---------------- edge phase: single-pass online softmax, fp16 gathers ----------------
__global__ void k_edge(float* __restrict__ out, int final_layer) {
    int gw = (blockIdx.x * blockDim.x + threadIdx.x) >> 5;
    int lane = threadIdx.x & 31;
    if (gw >= NN) return;
    int n = gw;
    int h = lane >> 3;
    float a2h = g_a2[n * 4 + h];
    int beg = g_off[n], end = g_off[n + 1];

    float m = -1e30f, ssum = 0.f;
    float acc[8] = {0, 0, 0, 0, 0, 0, 0, 0};

    if (beg < end) {
        int s = g_csr_src[beg];
        float a1v = g_a1[s * 4 + h];
        for (int i = beg; i < end; i++) {
            int s_nxt = 0; float a1_nxt = 0.f;
            if (i + 1 < end) {
                s_nxt = g_csr_src[i + 1];
                a1_nxt = g_a1[s_nxt * 4 + h];
            }
            float e = a1v + a2h;
            e = e > 0.f ? e : 0.2f * e;
            float mn = fmaxf(m, e);
            float sc = __expf(m - mn);
            float f = __expf(e - mn);
            ssum = ssum * sc + f;
            m = mn;
            // 8 halfs = 16B per lane
            uint4 q = *(const uint4*)(g_ft + (size_t)s * FD + lane * 8);
            float2 f0 = __half22float2(*(half2*)&q.x);
            float2 f1 = __half22float2(*(half2*)&q.y);
            float2 f2 = __half22float2(*(half2*)&q.z);
            float2 f3 = __half22float2(*(half2*)&q.w);
            acc[0] = acc[0] * sc + f0.x * f;  acc[1] = acc[1] * sc + f0.y * f;
            acc[2] = acc[2] * sc + f1.x * f;  acc[3] = acc[3] * sc + f1.y * f;
            acc[4] = acc[4] * sc + f2.x * f;  acc[5] = acc[5] * sc + f2.y * f;
            acc[6] = acc[6] * sc + f3.x * f;  acc[7] = acc[7] * sc + f3.y * f;
            s = s_nxt; a1v = a1_nxt;
        }
    }
    float inv = ssum > 0.f ? 1.0f / ssum : 0.f;
    #pragma unroll
    for (int j = 0; j < 8; j++) acc[j] *= inv;

    if (final_layer) {
        #pragma unroll
        for (int j = 0; j < 8; j++) {
            acc[j] += __shfl_xor_sync(0xffffffffu, acc[j], 8);
            acc[j] += __shfl_xor_sync(0xffffffffu, acc[j], 16);
        }
        if (lane < 8) {
            #pragma unroll
            for (int j = 0; j < 8; j++)
                out[n * 64 + lane * 8 + j] = acc[j] * 0.25f;
        }
    } else {
        float* d = g_hcat + (size_t)n * HSTR + lane * 8;
        #pragma unroll
        for (int j = 0; j < 8; j++) {
            float x = acc[j];
            x = x > 0.f ? x : expm1f(x);              // ELU
            d[j] = __uint_as_float(f2tf32(x));        // pre-round for next GEMM
        }
    }
}

// ---------------- launcher ----------------
extern "C" void kernel_launch(void* const* d_in, const int* in_sizes, int n_in,
                              void* d_out, int out_size) {
    const float* features = (const float*)d_in[0];
    const float* W0  = (const float*)d_in[1];
    const float* al0 = (const float*)d_in[2];
    const float* ar0 = (const float*)d_in[3];
    const float* pe0 = (const float*)d_in[4];
    const float* W1  = (const float*)d_in[5];
    const float* al1 = (const float*)d_in[6];
    const float* ar1 = (const float*)d_in[7];
    const float* pe1 = (const float*)d_in[8];
    const float* W2  = (const float*)d_in[9];
    const float* al2 = (const float*)d_in[10];
    const float* ar2 = (const float*)d_in[11];
    const float* pe2 = (const float*)d_in[12];
    const int* src = (const int*)d_in[13];
    const int* dst = (const int*)d_in[14];
    const int* pos = (const int*)d_in[15];
    float* out = (float*)d_out;

    float* Wr0 = nullptr; cudaGetSymbolAddress((void**)&Wr0, g_Wr);
    float* Wr1 = Wr0 + 288 * 256;
    float* Wr2 = Wr0 + 2 * 288 * 256;
    float* PW0 = nullptr; cudaGetSymbolAddress((void**)&PW0, g_PW);
    float* PW1 = PW0 + 3 * 256;
    float* PW2 = PW0 + 2 * 3 * 256;

    cudaFuncSetAttribute(k_gemm_tf32, cudaFuncAttributeMaxDynamicSharedMemorySize, GSMEM);

    dim3 ggrid(2, (NN + BM - 1) / BM);
    int edge_blocks = (NN + 7) / 8;

    // Ordered so the GEMM is the 4th launch (ncu capture lands on it).
    k_copy_feat<<<(NN * 128 + 255) / 256, 256>>>(features);               // 1
    k_round_all<<<(288 * 256 + 255) / 256, 256>>>(W0, W1, W2);            // 2
    k_pw<<<(3 * 3 * 256 + 255) / 256, 256>>>(pe0, pe1, pe2);              // 3
    k_gemm_tf32<<<ggrid, 256, GSMEM>>>(Wr0, 128, al0, ar0, PW0, pos);     // 4  <- profiled

    // CSR build
    k_zero_cnt<<<(NN + 255) / 256, 256>>>();                              // 5
    k_count<<<(EE + 255) / 256, 256>>>(dst);                              // 6
    k_scan<<<1, 1024>>>();                                                // 7
    k_place<<<(EE + 255) / 256, 256>>>(src, dst);                         // 8

    k_edge<<<edge_blocks, 256>>>(out, 0);                                 // 9

    k_gemm_tf32<<<ggrid, 256, GSMEM>>>(Wr1, 256, al1, ar1, PW1, pos);     // 10
    k_edge<<<edge_blocks, 256>>>(out, 0);                                 // 11

    k_gemm_tf32<<<ggrid, 256, GSMEM>>>(Wr2, 256, al2, ar2, PW2, pos);     // 12
    k_edge<<<edge_blocks, 256>>>(out, 1);                                 // 13
}

// round 10
// speedup vs baseline: 1.2571x; 1.1403x over previous
#include <cuda_runtime.h>
#include <cuda_bf16.h>
#include <cuda_fp16.h>
#include <cstdint>

#define NN 30000
#define EE 480000
#define HSTR 256      // hcat row stride (halfs)
#define FD 256        // ft row width (H*64)
#define WK 288        // WhT row stride (halfs)

// ---------------- scratch (device globals; no allocs allowed) ----------------
__device__ __half g_hcat[NN * HSTR];      // GEMM input rows (fp16)
__device__ __half g_ft[NN * FD];          // per-layer transformed features (fp16)
__device__ __half g_WhT[3 * 256 * WK];    // fp16 weights, transposed [l][n][k]
__device__ float  g_PW[3 * 3 * 256];      // pe[p] @ W_pe per layer (pos lookup)
__device__ float  g_a1[NN * 4];
__device__ float  g_a2[NN * 4];
__device__ int    g_cnt[NN];
__device__ int    g_off[NN + 1];
__device__ int    g_csr_src[EE];

// ---------------- input prep ----------------
__global__ void k_copy_feat(const float* __restrict__ f) {
    int i = blockIdx.x * blockDim.x + threadIdx.x;
    if (i < NN * 128) {
        int n = i >> 7, c = i & 127;
        g_hcat[n * HSTR + c] = __float2half_rn(f[i]);
    }
}

// WhT[l][n][k] = fp16(W_l[k][n])
__global__ void k_prep_w(const float* __restrict__ W0, const float* __restrict__ W1,
                         const float* __restrict__ W2) {
    int i = blockIdx.x * blockDim.x + threadIdx.x;
    if (i >= 256 * 288) return;
    int n = i & 255, k = i >> 8;
    if (k < 160)
        g_WhT[n * WK + k] = __float2half_rn(W0[k * 256 + n]);
    g_WhT[256 * WK + n * WK + k]     = __float2half_rn(W1[k * 256 + n]);
    g_WhT[2 * 256 * WK + n * WK + k] = __float2half_rn(W2[k * 256 + n]);
}

// PW[l][p][c] = sum_k fp16(pe_l[p,k]) * fp16(W_l[Kfeat+k, c])  (fp32 accumulate)
__global__ void k_pw(const float* __restrict__ pe0, const float* __restrict__ pe1,
                     const float* __restrict__ pe2) {
    int i = blockIdx.x * blockDim.x + threadIdx.x;
    if (i >= 3 * 3 * 256) return;
    int c = i & 255, p = (i >> 8) % 3, l = i / (3 * 256);
    const float* pe = (l == 0) ? pe0 : (l == 1 ? pe1 : pe2);
    int kf = (l == 0) ? 128 : 256;
    const __half* wrow = g_WhT + (size_t)l * 256 * WK + (size_t)c * WK + kf;
    float s = 0.f;
    #pragma unroll
    for (int k = 0; k < 32; k++)
        s += __half2float(__float2half_rn(pe[p * 32 + k])) * __half2float(wrow[k]);
    g_PW[(l * 3 + p) * 256 + c] = s;
}

// ---------------- CSR build ----------------
__global__ void k_zero_cnt() {
    int i = blockIdx.x * blockDim.x + threadIdx.x;
    if (i < NN) g_cnt[i] = 0;
}

__global__ void k_count(const int* __restrict__ dst) {
    int e = blockIdx.x * blockDim.x + threadIdx.x;
    if (e < EE) atomicAdd(&g_cnt[dst[e]], 1);
}

__global__ void k_scan() {
    __shared__ int warp_sums[32];
    __shared__ int s_carry;
    int tid = threadIdx.x;
    int lane = tid & 31, wid = tid >> 5;
    if (tid == 0) s_carry = 0;
    __syncthreads();
    for (int base = 0; base < NN; base += 1024) {
        int i = base + tid;
        int v = (i < NN) ? g_cnt[i] : 0;
        int x = v;
        #pragma unroll
        for (int d = 1; d < 32; d <<= 1) {
            int y = __shfl_up_sync(0xffffffffu, x, d);
            if (lane >= d) x += y;
        }
        if (lane == 31) warp_sums[wid] = x;
        __syncthreads();
        if (wid == 0) {
            int s = warp_sums[lane];
            #pragma unroll
            for (int d = 1; d < 32; d <<= 1) {
                int y = __shfl_up_sync(0xffffffffu, s, d);
                if (lane >= d) s += y;
            }
            warp_sums[lane] = s;
        }
        __syncthreads();
        int carry = s_carry;
        int excl = x - v + (wid > 0 ? warp_sums[wid - 1] : 0);
        if (i < NN) {
            g_off[i] = carry + excl;
            g_cnt[i] = carry + excl;
        }
        int chunk_total = warp_sums[31];
        __syncthreads();
        if (tid == 0) s_carry = carry + chunk_total;
        __syncthreads();
    }
    if (threadIdx.x == 0) g_off[NN] = s_carry;
}

__global__ void k_place(const int* __restrict__ src, const int* __restrict__ dst) {
    int e = blockIdx.x * blockDim.x + threadIdx.x;
    if (e < EE) {
        int p = atomicAdd(&g_cnt[dst[e]], 1);
        g_csr_src[p] = src[e];
    }
}

// ---------------- fp16 GEMM (m16n8k16) + PW add + fused a1/a2 epilogue ----------------
// Block 128x128, BK=32 halfs, 8 warps (4M x 2N, warp tile 32x64), 3-stage cp.async.
// A smem: [m][kw] words (kw=k/2), row stride 20 words -> lane-permutation banks.
// B smem: [n][kw] words, same stride (B = W^T rows), conflict-free.
#define BM 128
#define BN 128
#define BK 32
#define RSTR 20                        // words per smem row
#define ABYTES (BM * RSTR * 4)
#define BBYTES (BN * RSTR * 4)
#define GSMEM (3 * (ABYTES + BBYTES))

__device__ __forceinline__ void cpa16(uint32_t dst, const void* src, int sz) {
    asm volatile("cp.async.cg.shared.global [%0], [%1], 16, %2;\n"
                 :: "r"(dst), "l"(src), "r"(sz));
}

__global__ __launch_bounds__(256, 2) void k_gemm_f16(const __half* __restrict__ Wt, int K,
                                                     const float* __restrict__ al,
                                                     const float* __restrict__ ar,
                                                     const float* __restrict__ PWl,
                                                     const int* __restrict__ pos) {
    extern __shared__ char smem[];
    int bm = blockIdx.y * BM;
    int bn = blockIdx.x * BN;
    int tid = threadIdx.x;
    int lane = tid & 31, warp = tid >> 5;
    int warpM = warp & 3, warpN = warp >> 2;     // 4 x 2
    int gid = lane >> 2, tig = lane & 3;

    float c[2][8][4] = {};

    // cp.async chunks: A = 512 chunks (128 rows x 4x16B), B same; 2 each per thread
    int arow[2], aq[2], apred[2];
    const __half* asrc[2];
    uint32_t adst[2];
    int brow[2], bq[2];
    const __half* bsrc[2];
    uint32_t bdst[2];
    uint32_t sbase = (uint32_t)__cvta_generic_to_shared(smem);
    #pragma unroll
    for (int j = 0; j < 2; j++) {
        int ch = tid + j * 256;
        arow[j] = ch >> 2; aq[j] = ch & 3;
        apred[j] = (bm + arow[j]) < NN ? 16 : 0;
        asrc[j] = g_hcat + (size_t)(apred[j] ? bm + arow[j] : 0) * HSTR + aq[j] * 8;
        adst[j] = sbase + (arow[j] * RSTR + aq[j] * 4) * 4;
        brow[j] = ch >> 2; bq[j] = ch & 3;
        bsrc[j] = Wt + (size_t)(bn + brow[j]) * WK + bq[j] * 8;
        bdst[j] = sbase + 3 * ABYTES + (brow[j] * RSTR + bq[j] * 4) * 4;
    }

    int T = K / BK;

    #pragma unroll
    for (int j = 0; j < 2; j++) cpa16(adst[j], asrc[j], apred[j]);
    #pragma unroll
    for (int j = 0; j < 2; j++) cpa16(bdst[j], bsrc[j], 16);
    asm volatile("cp.async.commit_group;\n");
    if (T > 1) {
        #pragma unroll
        for (int j = 0; j < 2; j++) cpa16(adst[j] + ABYTES, asrc[j] + BK, apred[j]);
        #pragma unroll
        for (int j = 0; j < 2; j++) cpa16(bdst[j] + BBYTES, bsrc[j] + BK, 16);
        asm volatile("cp.async.commit_group;\n");
    }

    for (int t = 0; t < T; t++) {
        if (t + 1 < T)
            asm volatile("cp.async.wait_group 1;\n");
        else
            asm volatile("cp.async.wait_group 0;\n");
        __syncthreads();

        if (t + 2 < T) {
            int st = (t + 2) % 3;
            int k0 = (t + 2) * BK;
            #pragma unroll
            for (int j = 0; j < 2; j++) cpa16(adst[j] + st * ABYTES, asrc[j] + k0, apred[j]);
            #pragma unroll
            for (int j = 0; j < 2; j++) cpa16(bdst[j] + st * BBYTES, bsrc[j] + k0, 16);
            asm volatile("cp.async.commit_group;\n");
        }

        const uint32_t* Ac = (const uint32_t*)(smem + (t % 3) * ABYTES);
        const uint32_t* Bc = (const uint32_t*)(smem + 3 * ABYTES + (t % 3) * BBYTES);
        #pragma unroll
        for (int ks = 0; ks < BK; ks += 16) {
            int kw = ks >> 1;                      // word offset within row
            uint32_t a[2][4], b[8][2];
            #pragma unroll
            for (int mt = 0; mt < 2; mt++) {
                int m0 = warpM * 32 + mt * 16 + gid;
                a[mt][0] = Ac[m0 * RSTR + kw + tig];
                a[mt][1] = Ac[(m0 + 8) * RSTR + kw + tig];
                a[mt][2] = Ac[m0 * RSTR + kw + tig + 4];
                a[mt][3] = Ac[(m0 + 8) * RSTR + kw + tig + 4];
            }
            #pragma unroll
            for (int nt = 0; nt < 8; nt++) {
                int n0 = warpN * 64 + nt * 8 + gid;
                b[nt][0] = Bc[n0 * RSTR + kw + tig];
                b[nt][1] = Bc[n0 * RSTR + kw + tig + 4];
            }
            #pragma unroll
            for (int mt = 0; mt < 2; mt++)
                #pragma unroll
                for (int nt = 0; nt < 8; nt++)
                    asm volatile(
                        "mma.sync.aligned.m16n8k16.row.col.f32.f16.f16.f32 "
                        "{%0,%1,%2,%3}, {%4,%5,%6,%7}, {%8,%9}, {%0,%1,%2,%3};"
                        : "+f"(c[mt][nt][0]), "+f"(c[mt][nt][1]),
                          "+f"(c[mt][nt][2]), "+f"(c[mt][nt][3])
                        : "r"(a[mt][0]), "r"(a[mt][1]), "r"(a[mt][2]), "r"(a[mt][3]),
                          "r"(b[nt][0]), "r"(b[nt][1]));
        }
        __syncthreads();
    }

    // epilogue: += PW[pos[row]], store ft (fp16), fused a1/a2 row-dots
    int h = blockIdx.x * 2 + warpN;
    const float* alh = al + h * 64;
    const float* arh = ar + h * 64;
    float lw[8][2], rw[8][2];
    #pragma unroll
    for (int nt = 0; nt < 8; nt++) {
        int c64 = nt * 8 + tig * 2;
        lw[nt][0] = alh[c64]; lw[nt][1] = alh[c64 + 1];
        rw[nt][0] = arh[c64]; rw[nt][1] = arh[c64 + 1];
    }
    #pragma unroll
    for (int mt = 0; mt < 2; mt++) {
        int row0 = bm + warpM * 32 + mt * 16 + gid;
        int row1 = row0 + 8;
        const float* pw0 = PWl + (row0 < NN ? pos[row0] : 0) * 256;
        const float* pw1 = PWl + (row1 < NN ? pos[row1] : 0) * 256;
        float s1r0 = 0.f, s2r0 = 0.f, s1r1 = 0.f, s2r1 = 0.f;
        #pragma unroll
        for (int nt = 0; nt < 8; nt++) {
            int col = bn + warpN * 64 + nt * 8 + tig * 2;
            float v00 = c[mt][nt][0] + pw0[col], v01 = c[mt][nt][1] + pw0[col + 1];
            float v10 = c[mt][nt][2] + pw1[col], v11 = c[mt][nt][3] + pw1[col + 1];
            s1r0 += v00 * lw[nt][0] + v01 * lw[nt][1];
            s2r0 += v00 * rw[nt][0] + v01 * rw[nt][1];
            s1r1 += v10 * lw[nt][0] + v11 * lw[nt][1];
            s2r1 += v10 * rw[nt][0] + v11 * rw[nt][1];
            if (row0 < NN)
                *(half2*)(g_ft + (size_t)row0 * FD + col) = __floats2half2_rn(v00, v01);
            if (row1 < NN)
                *(half2*)(g_ft + (size_t)row1 * FD + col) = __floats2half2_rn(v10, v11);
        }
        #pragma unroll
        for (int d = 1; d < 4; d <<= 1) {
            s1r0 += __shfl_xor_sync(0xffffffffu, s1r0, d);
            s2r0 += __shfl_xor_sync(0xffffffffu, s2r0, d);
            s1r1 += __shfl_xor_sync(0xffffffffu, s1r1, d);
            s2r1 += __shfl_xor_sync(0xffffffffu, s2r1, d);
        }
        if (tig == 0) {
            if (row0 < NN) { g_a1[row0 * 4 + h] = s1r0; g_a2[row0 * 4 + h] = s2r0; }
            if (row1 < NN) { g_a1[row1 * 4 + h] = s1r1; g_a2[row1 * 4 + h] = s2r1; }
        }
    }
}

// ---------------- edge phase: single-pass online softmax, fp16 gathers ----------------
__global__ void k_edge(float* __restrict__ out, int final_layer) {
    int gw = (blockIdx.x * blockDim.x + threadIdx.x) >> 5;
    int lane = threadIdx.x & 31;
    if (gw >= NN) return;
    int n = gw;
    int h = lane >> 3;
    float a2h = g_a2[n * 4 + h];
    int beg = g_off[n], end = g_off[n + 1];

    float m = -1e30f, ssum = 0.f;
    float acc[8] = {0, 0, 0, 0, 0, 0, 0, 0};

    if (beg < end) {
        int s = g_csr_src[beg];
        float a1v = g_a1[s * 4 + h];
        for (int i = beg; i < end; i++) {
            int s_nxt = 0; float a1_nxt = 0.f;
            if (i + 1 < end) {
                s_nxt = g_csr_src[i + 1];
                a1_nxt = g_a1[s_nxt * 4 + h];
            }
            float e = a1v + a2h;
            e = e > 0.f ? e : 0.2f * e;
            float mn = fmaxf(m, e);
            float sc = __expf(m - mn);
            float f = __expf(e - mn);
            ssum = ssum * sc + f;
            m = mn;
            uint4 q = *(const uint4*)(g_ft + (size_t)s * FD + lane * 8);
            float2 f0 = __half22float2(*(half2*)&q.x);
            float2 f1 = __half22float2(*(half2*)&q.y);
            float2 f2 = __half22float2(*(half2*)&q.z);
            float2 f3 = __half22float2(*(half2*)&q.w);
            acc[0] = acc[0] * sc + f0.x * f;  acc[1] = acc[1] * sc + f0.y * f;
            acc[2] = acc[2] * sc + f1.x * f;  acc[3] = acc[3] * sc + f1.y * f;
            acc[4] = acc[4] * sc + f2.x * f;  acc[5] = acc[5] * sc + f2.y * f;
            acc[6] = acc[6] * sc + f3.x * f;  acc[7] = acc[7] * sc + f3.y * f;
            s = s_nxt; a1v = a1_nxt;
        }
    }
    float inv = ssum > 0.f ? 1.0f / ssum : 0.f;
    #pragma unroll
    for (int j = 0; j < 8; j++) acc[j] *= inv;

    if (final_layer) {
        #pragma unroll
        for (int j = 0; j < 8; j++) {
            acc[j] += __shfl_xor_sync(0xffffffffu, acc[j], 8);
            acc[j] += __shfl_xor_sync(0xffffffffu, acc[j], 16);
        }
        if (lane < 8) {
            #pragma unroll
            for (int j = 0; j < 8; j++)
                out[n * 64 + lane * 8 + j] = acc[j] * 0.25f;
        }
    } else {
        // ELU then fp16 for next GEMM's A
        half2 h0 = __floats2half2_rn(acc[0] > 0.f ? acc[0] : expm1f(acc[0]),
                                     acc[1] > 0.f ? acc[1] : expm1f(acc[1]));
        half2 h1 = __floats2half2_rn(acc[2] > 0.f ? acc[2] : expm1f(acc[2]),
                                     acc[3] > 0.f ? acc[3] : expm1f(acc[3]));
        half2 h2 = __floats2half2_rn(acc[4] > 0.f ? acc[4] : expm1f(acc[4]),
                                     acc[5] > 0.f ? acc[5] : expm1f(acc[5]));
        half2 h3 = __floats2half2_rn(acc[6] > 0.f ? acc[6] : expm1f(acc[6]),
                                     acc[7] > 0.f ? acc[7] : expm1f(acc[7]));
        uint4 q;
        q.x = *(uint32_t*)&h0; q.y = *(uint32_t*)&h1;
        q.z = *(uint32_t*)&h2; q.w = *(uint32_t*)&h3;
        *(uint4*)(g_hcat + (size_t)n * HSTR + lane * 8) = q;
    }
}

// ---------------- launcher ----------------
extern "C" void kernel_launch(void* const* d_in, const int* in_sizes, int n_in,
                              void* d_out, int out_size) {
    const float* features = (const float*)d_in[0];
    const float* W0  = (const float*)d_in[1];
    const float* al0 = (const float*)d_in[2];
    const float* ar0 = (const float*)d_in[3];
    const float* pe0 = (const float*)d_in[4];
    const float* W1  = (const float*)d_in[5];
    const float* al1 = (const float*)d_in[6];
    const float* ar1 = (const float*)d_in[7];
    const float* pe1 = (const float*)d_in[8];
    const float* W2  = (const float*)d_in[9];
    const float* al2 = (const float*)d_in[10];
    const float* ar2 = (const float*)d_in[11];
    const float* pe2 = (const float*)d_in[12];
    const int* src = (const int*)d_in[13];
    const int* dst = (const int*)d_in[14];
    const int* pos = (const int*)d_in[15];
    float* out = (float*)d_out;

    __half* Wt0 = nullptr; cudaGetSymbolAddress((void**)&Wt0, g_WhT);
    __half* Wt1 = Wt0 + 256 * WK;
    __half* Wt2 = Wt0 + 2 * 256 * WK;
    float* PW0 = nullptr; cudaGetSymbolAddress((void**)&PW0, g_PW);
    float* PW1 = PW0 + 3 * 256;
    float* PW2 = PW0 + 2 * 3 * 256;

    cudaFuncSetAttribute(k_gemm_f16, cudaFuncAttributeMaxDynamicSharedMemorySize, GSMEM);

    dim3 ggrid(2, (NN + BM - 1) / BM);
    int edge_blocks = (NN + 7) / 8;

    // Ordered so the GEMM is the 4th launch (ncu capture lands on it).
    k_copy_feat<<<(NN * 128 + 255) / 256, 256>>>(features);               // 1
    k_prep_w<<<(256 * 288 + 255) / 256, 256>>>(W0, W1, W2);               // 2
    k_pw<<<(3 * 3 * 256 + 255) / 256, 256>>>(pe0, pe1, pe2);              // 3
    k_gemm_f16<<<ggrid, 256, GSMEM>>>(Wt0, 128, al0, ar0, PW0, pos);      // 4  <- profiled

    // CSR build
    k_zero_cnt<<<(NN + 255) / 256, 256>>>();                              // 5
    k_count<<<(EE + 255) / 256, 256>>>(dst);                              // 6
    k_scan<<<1, 1024>>>();                                                // 7
    k_place<<<(EE + 255) / 256, 256>>>(src, dst);                         // 8

    k_edge<<<edge_blocks, 256>>>(out, 0);                                 // 9

    k_gemm_f16<<<ggrid, 256, GSMEM>>>(Wt1, 256, al1, ar1, PW1, pos);      // 10
    k_edge<<<edge_blocks, 256>>>(out, 0);                                 // 11

    k_gemm_f16<<<ggrid, 256, GSMEM>>>(Wt2, 256, al2, ar2, PW2, pos);      // 12
    k_edge<<<edge_blocks, 256>>>(out, 1);                                 // 13
}

// round 11
// speedup vs baseline: 1.2878x; 1.0244x over previous
#include <cuda_runtime.h>
#include <cuda_bf16.h>
#include <cuda_fp16.h>
#include <cstdint>

#define NN 30000
#define EE 480000
#define HSTR 256      // hcat row stride (halfs)
#define FD 256        // ft row width (H*64)
#define WK 288        // WhT row stride (halfs)

// ---------------- scratch (device globals; no allocs allowed) ----------------
__device__ __half g_hcat[NN * HSTR];      // GEMM input rows (fp16)
__device__ __half g_ft[NN * FD];          // per-layer transformed features (fp16)
__device__ __half g_WhT[3 * 256 * WK];    // fp16 weights, transposed [l][n][k]
__device__ float  g_PW[3 * 3 * 256];      // pe[p] @ W_pe per layer (pos lookup)
__device__ float  g_a1[NN * 4];
__device__ float  g_a2[NN * 4];
__device__ int    g_cnt[NN];
__device__ int    g_off[NN + 1];
__device__ int    g_csr_src[EE];

// ---------------- input prep ----------------
__global__ void k_copy_feat(const float* __restrict__ f) {
    int i = blockIdx.x * blockDim.x + threadIdx.x;
    if (i < NN * 128) {
        int n = i >> 7, c = i & 127;
        g_hcat[n * HSTR + c] = __float2half_rn(f[i]);
    }
}

__global__ void k_prep_w(const float* __restrict__ W0, const float* __restrict__ W1,
                         const float* __restrict__ W2) {
    int i = blockIdx.x * blockDim.x + threadIdx.x;
    if (i >= 256 * 288) return;
    int n = i & 255, k = i >> 8;
    if (k < 160)
        g_WhT[n * WK + k] = __float2half_rn(W0[k * 256 + n]);
    g_WhT[256 * WK + n * WK + k]     = __float2half_rn(W1[k * 256 + n]);
    g_WhT[2 * 256 * WK + n * WK + k] = __float2half_rn(W2[k * 256 + n]);
}

__global__ void k_pw(const float* __restrict__ pe0, const float* __restrict__ pe1,
                     const float* __restrict__ pe2) {
    int i = blockIdx.x * blockDim.x + threadIdx.x;
    if (i >= 3 * 3 * 256) return;
    int c = i & 255, p = (i >> 8) % 3, l = i / (3 * 256);
    const float* pe = (l == 0) ? pe0 : (l == 1 ? pe1 : pe2);
    int kf = (l == 0) ? 128 : 256;
    const __half* wrow = g_WhT + (size_t)l * 256 * WK + (size_t)c * WK + kf;
    float s = 0.f;
    #pragma unroll
    for (int k = 0; k < 32; k++)
        s += __half2float(__float2half_rn(pe[p * 32 + k])) * __half2float(wrow[k]);
    g_PW[(l * 3 + p) * 256 + c] = s;
}

// ---------------- CSR build ----------------
__global__ void k_zero_cnt() {
    int i = blockIdx.x * blockDim.x + threadIdx.x;
    if (i < NN) g_cnt[i] = 0;
}

__global__ void k_count(const int* __restrict__ dst) {
    int e = blockIdx.x * blockDim.x + threadIdx.x;
    if (e < EE) atomicAdd(&g_cnt[dst[e]], 1);
}

__global__ void k_scan() {
    __shared__ int warp_sums[32];
    __shared__ int s_carry;
    int tid = threadIdx.x;
    int lane = tid & 31, wid = tid >> 5;
    if (tid == 0) s_carry = 0;
    __syncthreads();
    for (int base = 0; base < NN; base += 1024) {
        int i = base + tid;
        int v = (i < NN) ? g_cnt[i] : 0;
        int x = v;
        #pragma unroll
        for (int d = 1; d < 32; d <<= 1) {
            int y = __shfl_up_sync(0xffffffffu, x, d);
            if (lane >= d) x += y;
        }
        if (lane == 31) warp_sums[wid] = x;
        __syncthreads();
        if (wid == 0) {
            int s = warp_sums[lane];
            #pragma unroll
            for (int d = 1; d < 32; d <<= 1) {
                int y = __shfl_up_sync(0xffffffffu, s, d);
                if (lane >= d) s += y;
            }
            warp_sums[lane] = s;
        }
        __syncthreads();
        int carry = s_carry;
        int excl = x - v + (wid > 0 ? warp_sums[wid - 1] : 0);
        if (i < NN) {
            g_off[i] = carry + excl;
            g_cnt[i] = carry + excl;
        }
        int chunk_total = warp_sums[31];
        __syncthreads();
        if (tid == 0) s_carry = carry + chunk_total;
        __syncthreads();
    }
    if (threadIdx.x == 0) g_off[NN] = s_carry;
}

__global__ void k_place(const int* __restrict__ src, const int* __restrict__ dst) {
    int e = blockIdx.x * blockDim.x + threadIdx.x;
    if (e < EE) {
        int p = atomicAdd(&g_cnt[dst[e]], 1);
        g_csr_src[p] = src[e];
    }
}

// ---------------- fp16 GEMM (m16n8k16 + ldmatrix) + PW add + fused epilogue ----------------
// Block 128x128, BK=32 halfs, 8 warps (4M x 2N), 3-stage cp.async.
// A/B smem rows: 16 data words + 4 pad (RSTR=20) -> 8-row LDSM phases cover all banks.
#define BM 128
#define BN 128
#define BK 32
#define RSTR 20
#define ABYTES (BM * RSTR * 4)
#define BBYTES (BN * RSTR * 4)
#define GSMEM (3 * (ABYTES + BBYTES))

__device__ __forceinline__ void cpa16(uint32_t dst, const void* src, int sz) {
    asm volatile("cp.async.cg.shared.global [%0], [%1], 16, %2;\n"
                 :: "r"(dst), "l"(src), "r"(sz));
}

__device__ __forceinline__ void ldsm4(uint32_t& r0, uint32_t& r1, uint32_t& r2, uint32_t& r3,
                                      uint32_t addr) {
    asm volatile("ldmatrix.sync.aligned.m8n8.x4.shared.b16 {%0,%1,%2,%3}, [%4];"
                 : "=r"(r0), "=r"(r1), "=r"(r2), "=r"(r3) : "r"(addr));
}

__global__ __launch_bounds__(256, 2) void k_gemm_f16(const __half* __restrict__ Wt, int K,
                                                     const float* __restrict__ al,
                                                     const float* __restrict__ ar,
                                                     const float* __restrict__ PWl,
                                                     const int* __restrict__ pos) {
    extern __shared__ char smem[];
    int bm = blockIdx.y * BM;
    int bn = blockIdx.x * BN;
    int tid = threadIdx.x;
    int lane = tid & 31, warp = tid >> 5;
    int warpM = warp & 3, warpN = warp >> 2;     // 4 x 2
    int gid = lane >> 2, tig = lane & 3;

    float c[2][8][4] = {};

    // cp.async chunk assignments (2 A + 2 B per thread)
    int arow[2], aq[2], apred[2];
    const __half* asrc[2];
    uint32_t adst[2];
    const __half* bsrc[2];
    uint32_t bdst[2];
    uint32_t sbase = (uint32_t)__cvta_generic_to_shared(smem);
    #pragma unroll
    for (int j = 0; j < 2; j++) {
        int ch = tid + j * 256;
        arow[j] = ch >> 2; aq[j] = ch & 3;
        apred[j] = (bm + arow[j]) < NN ? 16 : 0;
        asrc[j] = g_hcat + (size_t)(apred[j] ? bm + arow[j] : 0) * HSTR + aq[j] * 8;
        adst[j] = sbase + (arow[j] * RSTR + aq[j] * 4) * 4;
        bsrc[j] = Wt + (size_t)(bn + arow[j]) * WK + aq[j] * 8;
        bdst[j] = sbase + 3 * ABYTES + (arow[j] * RSTR + aq[j] * 4) * 4;
    }

    // ldmatrix per-lane word offsets (within one buffer, kw=0)
    int lg = lane >> 3, lr = lane & 7;           // matrix group / row-in-matrix
    uint32_t aoffw[2], boffw[4];
    #pragma unroll
    for (int mt = 0; mt < 2; mt++) {
        int m0 = warpM * 32 + mt * 16;
        aoffw[mt] = (uint32_t)((m0 + (lg & 1) * 8 + lr) * RSTR + (lg >> 1) * 4);
    }
    #pragma unroll
    for (int np = 0; np < 4; np++) {
        int n0 = warpN * 64 + np * 16;
        boffw[np] = (uint32_t)((n0 + (lg >> 1) * 8 + lr) * RSTR + (lg & 1) * 4);
    }

    int T = K / BK;

    #pragma unroll
    for (int j = 0; j < 2; j++) cpa16(adst[j], asrc[j], apred[j]);
    #pragma unroll
    for (int j = 0; j < 2; j++) cpa16(bdst[j], bsrc[j], 16);
    asm volatile("cp.async.commit_group;\n");
    if (T > 1) {
        #pragma unroll
        for (int j = 0; j < 2; j++) cpa16(adst[j] + ABYTES, asrc[j] + BK, apred[j]);
        #pragma unroll
        for (int j = 0; j < 2; j++) cpa16(bdst[j] + BBYTES, bsrc[j] + BK, 16);
        asm volatile("cp.async.commit_group;\n");
    }

    for (int t = 0; t < T; t++) {
        if (t + 1 < T)
            asm volatile("cp.async.wait_group 1;\n");
        else
            asm volatile("cp.async.wait_group 0;\n");
        __syncthreads();

        if (t + 2 < T) {
            int st = (t + 2) % 3;
            int k0 = (t + 2) * BK;
            #pragma unroll
            for (int j = 0; j < 2; j++) cpa16(adst[j] + st * ABYTES, asrc[j] + k0, apred[j]);
            #pragma unroll
            for (int j = 0; j < 2; j++) cpa16(bdst[j] + st * BBYTES, bsrc[j] + k0, 16);
            asm volatile("cp.async.commit_group;\n");
        }

        uint32_t abase = sbase + (t % 3) * ABYTES;
        uint32_t bbase = sbase + 3 * ABYTES + (t % 3) * BBYTES;
        #pragma unroll
        for (int ks = 0; ks < BK; ks += 16) {
            uint32_t kb = (uint32_t)((ks >> 1) * 4);   // byte offset of kw
            uint32_t a[2][4], b[8][2];
            #pragma unroll
            for (int mt = 0; mt < 2; mt++)
                ldsm4(a[mt][0], a[mt][1], a[mt][2], a[mt][3],
                      abase + aoffw[mt] * 4 + kb);
            #pragma unroll
            for (int np = 0; np < 4; np++)
                ldsm4(b[2 * np][0], b[2 * np][1], b[2 * np + 1][0], b[2 * np + 1][1],
                      bbase + boffw[np] * 4 + kb);
            #pragma unroll
            for (int mt = 0; mt < 2; mt++)
                #pragma unroll
                for (int nt = 0; nt < 8; nt++)
                    asm volatile(
                        "mma.sync.aligned.m16n8k16.row.col.f32.f16.f16.f32 "
                        "{%0,%1,%2,%3}, {%4,%5,%6,%7}, {%8,%9}, {%0,%1,%2,%3};"
                        : "+f"(c[mt][nt][0]), "+f"(c[mt][nt][1]),
                          "+f"(c[mt][nt][2]), "+f"(c[mt][nt][3])
                        : "r"(a[mt][0]), "r"(a[mt][1]), "r"(a[mt][2]), "r"(a[mt][3]),
                          "r"(b[nt][0]), "r"(b[nt][1]));
        }
        __syncthreads();
    }

    // epilogue: += PW[pos[row]], store ft (fp16), fused a1/a2 row-dots
    int h = blockIdx.x * 2 + warpN;
    const float* alh = al + h * 64;
    const float* arh = ar + h * 64;
    float lw[8][2], rw[8][2];
    #pragma unroll
    for (int nt = 0; nt < 8; nt++) {
        int c64 = nt * 8 + tig * 2;
        lw[nt][0] = alh[c64]; lw[nt][1] = alh[c64 + 1];
        rw[nt][0] = arh[c64]; rw[nt][1] = arh[c64 + 1];
    }
    #pragma unroll
    for (int mt = 0; mt < 2; mt++) {
        int row0 = bm + warpM * 32 + mt * 16 + gid;
        int row1 = row0 + 8;
        const float* pw0 = PWl + (row0 < NN ? pos[row0] : 0) * 256;
        const float* pw1 = PWl + (row1 < NN ? pos[row1] : 0) * 256;
        float s1r0 = 0.f, s2r0 = 0.f, s1r1 = 0.f, s2r1 = 0.f;
        #pragma unroll
        for (int nt = 0; nt < 8; nt++) {
            int col = bn + warpN * 64 + nt * 8 + tig * 2;
            float v00 = c[mt][nt][0] + pw0[col], v01 = c[mt][nt][1] + pw0[col + 1];
            float v10 = c[mt][nt][2] + pw1[col], v11 = c[mt][nt][3] + pw1[col + 1];
            s1r0 += v00 * lw[nt][0] + v01 * lw[nt][1];
            s2r0 += v00 * rw[nt][0] + v01 * rw[nt][1];
            s1r1 += v10 * lw[nt][0] + v11 * lw[nt][1];
            s2r1 += v10 * rw[nt][0] + v11 * rw[nt][1];
            if (row0 < NN)
                *(half2*)(g_ft + (size_t)row0 * FD + col) = __floats2half2_rn(v00, v01);
            if (row1 < NN)
                *(half2*)(g_ft + (size_t)row1 * FD + col) = __floats2half2_rn(v10, v11);
        }
        #pragma unroll
        for (int d = 1; d < 4; d <<= 1) {
            s1r0 += __shfl_xor_sync(0xffffffffu, s1r0, d);
            s2r0 += __shfl_xor_sync(0xffffffffu, s2r0, d);
            s1r1 += __shfl_xor_sync(0xffffffffu, s1r1, d);
            s2r1 += __shfl_xor_sync(0xffffffffu, s2r1, d);
        }
        if (tig == 0) {
            if (row0 < NN) { g_a1[row0 * 4 + h] = s1r0; g_a2[row0 * 4 + h] = s2r0; }
            if (row1 < NN) { g_a1[row1 * 4 + h] = s1r1; g_a2[row1 * 4 + h] = s2r1; }
        }
    }
}

// ---------------- edge phase: single-pass online softmax, fp16 gathers ----------------
__global__ void k_edge(float* __restrict__ out, int final_layer) {
    int gw = (blockIdx.x * blockDim.x + threadIdx.x) >> 5;
    int lane = threadIdx.x & 31;
    if (gw >= NN) return;
    int n = gw;
    int h = lane >> 3;
    float a2h = g_a2[n * 4 + h];
    int beg = g_off[n], end = g_off[n + 1];

    float m = -1e30f, ssum = 0.f;
    float acc[8] = {0, 0, 0, 0, 0, 0, 0, 0};

    if (beg < end) {
        int s = g_csr_src[beg];
        float a1v = g_a1[s * 4 + h];
        for (int i = beg; i < end; i++) {
            int s_nxt = 0; float a1_nxt = 0.f;
            if (i + 1 < end) {
                s_nxt = g_csr_src[i + 1];
                a1_nxt = g_a1[s_nxt * 4 + h];
            }
            float e = a1v + a2h;
            e = e > 0.f ? e : 0.2f * e;
            float mn = fmaxf(m, e);
            float sc = __expf(m - mn);
            float f = __expf(e - mn);
            ssum = ssum * sc + f;
            m = mn;
            uint4 q = *(const uint4*)(g_ft + (size_t)s * FD + lane * 8);
            float2 f0 = __half22float2(*(half2*)&q.x);
            float2 f1 = __half22float2(*(half2*)&q.y);
            float2 f2 = __half22float2(*(half2*)&q.z);
            float2 f3 = __half22float2(*(half2*)&q.w);
            acc[0] = acc[0] * sc + f0.x * f;  acc[1] = acc[1] * sc + f0.y * f;
            acc[2] = acc[2] * sc + f1.x * f;  acc[3] = acc[3] * sc + f1.y * f;
            acc[4] = acc[4] * sc + f2.x * f;  acc[5] = acc[5] * sc + f2.y * f;
            acc[6] = acc[6] * sc + f3.x * f;  acc[7] = acc[7] * sc + f3.y * f;
            s = s_nxt; a1v = a1_nxt;
        }
    }
    float inv = ssum > 0.f ? 1.0f / ssum : 0.f;
    #pragma unroll
    for (int j = 0; j < 8; j++) acc[j] *= inv;

    if (final_layer) {
        #pragma unroll
        for (int j = 0; j < 8; j++) {
            acc[j] += __shfl_xor_sync(0xffffffffu, acc[j], 8);
            acc[j] += __shfl_xor_sync(0xffffffffu, acc[j], 16);
        }
        if (lane < 8) {
            #pragma unroll
            for (int j = 0; j < 8; j++)
                out[n * 64 + lane * 8 + j] = acc[j] * 0.25f;
        }
    } else {
        half2 h0 = __floats2half2_rn(acc[0] > 0.f ? acc[0] : expm1f(acc[0]),
                                     acc[1] > 0.f ? acc[1] : expm1f(acc[1]));
        half2 h1 = __floats2half2_rn(acc[2] > 0.f ? acc[2] : expm1f(acc[2]),
                                     acc[3] > 0.f ? acc[3] : expm1f(acc[3]));
        half2 h2 = __floats2half2_rn(acc[4] > 0.f ? acc[4] : expm1f(acc[4]),
                                     acc[5] > 0.f ? acc[5] : expm1f(acc[5]));
        half2 h3 = __floats2half2_rn(acc[6] > 0.f ? acc[6] : expm1f(acc[6]),
                                     acc[7] > 0.f ? acc[7] : expm1f(acc[7]));
        uint4 q;
        q.x = *(uint32_t*)&h0; q.y = *(uint32_t*)&h1;
        q.z = *(uint32_t*)&h2; q.w = *(uint32_t*)&h3;
        *(uint4*)(g_hcat + (size_t)n * HSTR + lane * 8) = q;
    }
}

// ---------------- launcher ----------------
extern "C" void kernel_launch(void* const* d_in, const int* in_sizes, int n_in,
                              void* d_out, int out_size) {
    const float* features = (const float*)d_in[0];
    const float* W0  = (const float*)d_in[1];
    const float* al0 = (const float*)d_in[2];
    const float* ar0 = (const float*)d_in[3];
    const float* pe0 = (const float*)d_in[4];
    const float* W1  = (const float*)d_in[5];
    const float* al1 = (const float*)d_in[6];
    const float* ar1 = (const float*)d_in[7];
    const float* pe1 = (const float*)d_in[8];
    const float* W2  = (const float*)d_in[9];
    const float* al2 = (const float*)d_in[10];
    const float* ar2 = (const float*)d_in[11];
    const float* pe2 = (const float*)d_in[12];
    const int* src = (const int*)d_in[13];
    const int* dst = (const int*)d_in[14];
    const int* pos = (const int*)d_in[15];
    float* out = (float*)d_out;

    __half* Wt0 = nullptr; cudaGetSymbolAddress((void**)&Wt0, g_WhT);
    __half* Wt1 = Wt0 + 256 * WK;
    __half* Wt2 = Wt0 + 2 * 256 * WK;
    float* PW0 = nullptr; cudaGetSymbolAddress((void**)&PW0, g_PW);
    float* PW1 = PW0 + 3 * 256;
    float* PW2 = PW0 + 2 * 3 * 256;

    cudaFuncSetAttribute(k_gemm_f16, cudaFuncAttributeMaxDynamicSharedMemorySize, GSMEM);

    dim3 ggrid(2, (NN + BM - 1) / BM);
    int edge_blocks = (NN + 7) / 8;

    // Ordered so the GEMM is the 4th launch (ncu capture lands on it).
    k_copy_feat<<<(NN * 128 + 255) / 256, 256>>>(features);               // 1
    k_prep_w<<<(256 * 288 + 255) / 256, 256>>>(W0, W1, W2);               // 2
    k_pw<<<(3 * 3 * 256 + 255) / 256, 256>>>(pe0, pe1, pe2);              // 3
    k_gemm_f16<<<ggrid, 256, GSMEM>>>(Wt0, 128, al0, ar0, PW0, pos);      // 4  <- profiled

    // CSR build
    k_zero_cnt<<<(NN + 255) / 256, 256>>>();                              // 5
    k_count<<<(EE + 255) / 256, 256>>>(dst);                              // 6
    k_scan<<<1, 1024>>>();                                                // 7
    k_place<<<(EE + 255) / 256, 256>>>(src, dst);                         // 8

    k_edge<<<edge_blocks, 256>>>(out, 0);                                 // 9

    k_gemm_f16<<<ggrid, 256, GSMEM>>>(Wt1, 256, al1, ar1, PW1, pos);      // 10
    k_edge<<<edge_blocks, 256>>>(out, 0);                                 // 11

    k_gemm_f16<<<ggrid, 256, GSMEM>>>(Wt2, 256, al2, ar2, PW2, pos);      // 12
    k_edge<<<edge_blocks, 256>>>(out, 1);                                 // 13
}

// round 12
// speedup vs baseline: 1.3507x; 1.0489x over previous
#include <cuda_runtime.h>
#include <cuda_bf16.h>
#include <cuda_fp16.h>
#include <cstdint>

#define NN 30000
#define EE 480000
#define HSTR 256      // hcat row stride (halfs)
#define FD 256        // ft row width (H*64)
#define WK 288        // WhT row stride (halfs)

// ---------------- scratch (device globals; no allocs allowed) ----------------
__device__ __half g_hcat[NN * HSTR];      // GEMM input rows (fp16)
__device__ __half g_ft[NN * FD];          // per-layer transformed features (fp16)
__device__ __half g_WhT[3 * 256 * WK];    // fp16 weights, transposed [l][n][k]
__device__ float  g_PW[3 * 3 * 256];      // pe[p] @ W_pe per layer (pos lookup)
__device__ float  g_a1[NN * 4];
__device__ float  g_a2[NN * 4];
__device__ int    g_cnt[NN];              // zero at call entry (init or prev call's reset)
__device__ int    g_off[NN + 1];
__device__ int    g_csr_src[EE];

// ---------------- fused prep: feat copy + W transpose + PW + edge count ----------------
// Section blocks: [0, 3750)   copy_feat (half4 vectorized)
//                 [3750, 4038) prep_w
//                 [4038, 4047) pw (reads raw W -> no intra-kernel race)
//                 [4047, 5922) count
#define PB_FEAT 3750
#define PB_W    288
#define PB_PW   9
#define PB_CNT  1875
#define PB_TOT  (PB_FEAT + PB_W + PB_PW + PB_CNT)

__global__ void k_prep(const float* __restrict__ f,
                       const float* __restrict__ W0, const float* __restrict__ W1,
                       const float* __restrict__ W2,
                       const float* __restrict__ pe0, const float* __restrict__ pe1,
                       const float* __restrict__ pe2,
                       const int* __restrict__ dst) {
    int b = blockIdx.x;
    if (b < PB_FEAT) {
        // 960000 half4-groups
        int idx = b * 256 + threadIdx.x;
        if (idx < NN * 32) {
            int n = idx >> 5, q = idx & 31;
            float4 v = *(const float4*)(f + (size_t)n * 128 + q * 4);
            half2 h0 = __floats2half2_rn(v.x, v.y);
            half2 h1 = __floats2half2_rn(v.z, v.w);
            uint2 o;
            o.x = *(uint32_t*)&h0; o.y = *(uint32_t*)&h1;
            *(uint2*)(g_hcat + (size_t)n * HSTR + q * 4) = o;
        }
    } else if (b < PB_FEAT + PB_W) {
        int i = (b - PB_FEAT) * 256 + threadIdx.x;
        if (i < 256 * 288) {
            int n = i & 255, k = i >> 8;
            if (k < 160)
                g_WhT[n * WK + k] = __float2half_rn(W0[k * 256 + n]);
            g_WhT[256 * WK + n * WK + k]     = __float2half_rn(W1[k * 256 + n]);
            g_WhT[2 * 256 * WK + n * WK + k] = __float2half_rn(W2[k * 256 + n]);
        }
    } else if (b < PB_FEAT + PB_W + PB_PW) {
        int i = (b - PB_FEAT - PB_W) * 256 + threadIdx.x;
        if (i < 3 * 3 * 256) {
            int c = i & 255, p = (i >> 8) % 3, l = i / (3 * 256);
            const float* pe = (l == 0) ? pe0 : (l == 1 ? pe1 : pe2);
            const float* W = (l == 0) ? W0 : (l == 1 ? W1 : W2);
            int kf = (l == 0) ? 128 : 256;
            float s = 0.f;
            #pragma unroll
            for (int k = 0; k < 32; k++)
                s += __half2float(__float2half_rn(pe[p * 32 + k])) *
                     __half2float(__float2half_rn(W[(kf + k) * 256 + c]));
            g_PW[(l * 3 + p) * 256 + c] = s;
        }
    } else {
        int e = (b - PB_FEAT - PB_W - PB_PW) * 256 + threadIdx.x;
        if (e < EE) atomicAdd(&g_cnt[dst[e]], 1);
    }
}

// ---------------- CSR scan + place ----------------
__global__ void k_scan() {
    __shared__ int warp_sums[32];
    __shared__ int s_carry;
    int tid = threadIdx.x;
    int lane = tid & 31, wid = tid >> 5;
    if (tid == 0) s_carry = 0;
    __syncthreads();
    for (int base = 0; base < NN; base += 1024) {
        int i = base + tid;
        int v = (i < NN) ? g_cnt[i] : 0;
        int x = v;
        #pragma unroll
        for (int d = 1; d < 32; d <<= 1) {
            int y = __shfl_up_sync(0xffffffffu, x, d);
            if (lane >= d) x += y;
        }
        if (lane == 31) warp_sums[wid] = x;
        __syncthreads();
        if (wid == 0) {
            int s = warp_sums[lane];
            #pragma unroll
            for (int d = 1; d < 32; d <<= 1) {
                int y = __shfl_up_sync(0xffffffffu, s, d);
                if (lane >= d) s += y;
            }
            warp_sums[lane] = s;
        }
        __syncthreads();
        int carry = s_carry;
        int excl = x - v + (wid > 0 ? warp_sums[wid - 1] : 0);
        if (i < NN) {
            g_off[i] = carry + excl;
            g_cnt[i] = carry + excl;
        }
        int chunk_total = warp_sums[31];
        __syncthreads();
        if (tid == 0) s_carry = carry + chunk_total;
        __syncthreads();
    }
    if (threadIdx.x == 0) g_off[NN] = s_carry;
}

__global__ void k_place(const int* __restrict__ src, const int* __restrict__ dst) {
    int e = blockIdx.x * blockDim.x + threadIdx.x;
    if (e < EE) {
        int p = atomicAdd(&g_cnt[dst[e]], 1);
        g_csr_src[p] = src[e];
    }
}

// ---------------- fp16 GEMM (m16n8k16 + ldmatrix) + PW add + fused epilogue ----------------
#define BM 128
#define BN 128
#define BK 32
#define RSTR 20
#define ABYTES (BM * RSTR * 4)
#define BBYTES (BN * RSTR * 4)
#define GSMEM (3 * (ABYTES + BBYTES))

__device__ __forceinline__ void cpa16(uint32_t dst, const void* src, int sz) {
    asm volatile("cp.async.cg.shared.global [%0], [%1], 16, %2;\n"
                 :: "r"(dst), "l"(src), "r"(sz));
}

__device__ __forceinline__ void ldsm4(uint32_t& r0, uint32_t& r1, uint32_t& r2, uint32_t& r3,
                                      uint32_t addr) {
    asm volatile("ldmatrix.sync.aligned.m8n8.x4.shared.b16 {%0,%1,%2,%3}, [%4];"
                 : "=r"(r0), "=r"(r1), "=r"(r2), "=r"(r3) : "r"(addr));
}

__global__ __launch_bounds__(256, 2) void k_gemm_f16(const __half* __restrict__ Wt, int K,
                                                     const float* __restrict__ al,
                                                     const float* __restrict__ ar,
                                                     const float* __restrict__ PWl,
                                                     const int* __restrict__ pos) {
    extern __shared__ char smem[];
    int bm = blockIdx.y * BM;
    int bn = blockIdx.x * BN;
    int tid = threadIdx.x;
    int lane = tid & 31, warp = tid >> 5;
    int warpM = warp & 3, warpN = warp >> 2;     // 4 x 2
    int gid = lane >> 2, tig = lane & 3;

    float c[2][8][4] = {};

    int arow[2], aq[2], apred[2];
    const __half* asrc[2];
    uint32_t adst[2];
    const __half* bsrc[2];
    uint32_t bdst[2];
    uint32_t sbase = (uint32_t)__cvta_generic_to_shared(smem);
    #pragma unroll
    for (int j = 0; j < 2; j++) {
        int ch = tid + j * 256;
        arow[j] = ch >> 2; aq[j] = ch & 3;
        apred[j] = (bm + arow[j]) < NN ? 16 : 0;
        asrc[j] = g_hcat + (size_t)(apred[j] ? bm + arow[j] : 0) * HSTR + aq[j] * 8;
        adst[j] = sbase + (arow[j] * RSTR + aq[j] * 4) * 4;
        bsrc[j] = Wt + (size_t)(bn + arow[j]) * WK + aq[j] * 8;
        bdst[j] = sbase + 3 * ABYTES + (arow[j] * RSTR + aq[j] * 4) * 4;
    }

    // ldmatrix per-lane word offsets
    int lg = lane >> 3, lr = lane & 7;
    uint32_t aoffw[2], boffw[4];
    #pragma unroll
    for (int mt = 0; mt < 2; mt++) {
        int m0 = warpM * 32 + mt * 16;
        aoffw[mt] = (uint32_t)((m0 + (lg & 1) * 8 + lr) * RSTR + (lg >> 1) * 4);
    }
    #pragma unroll
    for (int np = 0; np < 4; np++) {
        int n0 = warpN * 64 + np * 16;
        boffw[np] = (uint32_t)((n0 + (lg >> 1) * 8 + lr) * RSTR + (lg & 1) * 4);
    }

    // prefetch epilogue row metadata early (hides pos gather under mainloop)
    int row0a = bm + warpM * 32 + gid;
    int row1a = row0a + 8;
    int row0b = row0a + 16, row1b = row0a + 24;
    int p0a = (row0a < NN) ? pos[row0a] : 0;
    int p1a = (row1a < NN) ? pos[row1a] : 0;
    int p0b = (row0b < NN) ? pos[row0b] : 0;
    int p1b = (row1b < NN) ? pos[row1b] : 0;

    int T = K / BK;

    #pragma unroll
    for (int j = 0; j < 2; j++) cpa16(adst[j], asrc[j], apred[j]);
    #pragma unroll
    for (int j = 0; j < 2; j++) cpa16(bdst[j], bsrc[j], 16);
    asm volatile("cp.async.commit_group;\n");
    if (T > 1) {
        #pragma unroll
        for (int j = 0; j < 2; j++) cpa16(adst[j] + ABYTES, asrc[j] + BK, apred[j]);
        #pragma unroll
        for (int j = 0; j < 2; j++) cpa16(bdst[j] + BBYTES, bsrc[j] + BK, 16);
        asm volatile("cp.async.commit_group;\n");
    }

    for (int t = 0; t < T; t++) {
        if (t + 1 < T)
            asm volatile("cp.async.wait_group 1;\n");
        else
            asm volatile("cp.async.wait_group 0;\n");
        __syncthreads();   // also orders: all warps done reading buffer (t+2)%3 from iter t-1

        if (t + 2 < T) {
            int st = (t + 2) % 3;
            int k0 = (t + 2) * BK;
            #pragma unroll
            for (int j = 0; j < 2; j++) cpa16(adst[j] + st * ABYTES, asrc[j] + k0, apred[j]);
            #pragma unroll
            for (int j = 0; j < 2; j++) cpa16(bdst[j] + st * BBYTES, bsrc[j] + k0, 16);
            asm volatile("cp.async.commit_group;\n");
        }

        uint32_t abase = sbase + (t % 3) * ABYTES;
        uint32_t bbase = sbase + 3 * ABYTES + (t % 3) * BBYTES;
        #pragma unroll
        for (int ks = 0; ks < BK; ks += 16) {
            uint32_t kb = (uint32_t)((ks >> 1) * 4);
            uint32_t a[2][4], b[8][2];
            #pragma unroll
            for (int mt = 0; mt < 2; mt++)
                ldsm4(a[mt][0], a[mt][1], a[mt][2], a[mt][3],
                      abase + aoffw[mt] * 4 + kb);
            #pragma unroll
            for (int np = 0; np < 4; np++)
                ldsm4(b[2 * np][0], b[2 * np][1], b[2 * np + 1][0], b[2 * np + 1][1],
                      bbase + boffw[np] * 4 + kb);
            #pragma unroll
            for (int mt = 0; mt < 2; mt++)
                #pragma unroll
                for (int nt = 0; nt < 8; nt++)
                    asm volatile(
                        "mma.sync.aligned.m16n8k16.row.col.f32.f16.f16.f32 "
                        "{%0,%1,%2,%3}, {%4,%5,%6,%7}, {%8,%9}, {%0,%1,%2,%3};"
                        : "+f"(c[mt][nt][0]), "+f"(c[mt][nt][1]),
                          "+f"(c[mt][nt][2]), "+f"(c[mt][nt][3])
                        : "r"(a[mt][0]), "r"(a[mt][1]), "r"(a[mt][2]), "r"(a[mt][3]),
                          "r"(b[nt][0]), "r"(b[nt][1]));
        }
        // no trailing __syncthreads: next iteration's leading barrier provides the ordering
    }
    __syncthreads();

    // epilogue: += PW[pos[row]], store ft (fp16), fused a1/a2 row-dots
    int h = blockIdx.x * 2 + warpN;
    const float* alh = al + h * 64;
    const float* arh = ar + h * 64;
    float lw[8][2], rw[8][2];
    #pragma unroll
    for (int nt = 0; nt < 8; nt++) {
        int c64 = nt * 8 + tig * 2;
        lw[nt][0] = alh[c64]; lw[nt][1] = alh[c64 + 1];
        rw[nt][0] = arh[c64]; rw[nt][1] = arh[c64 + 1];
    }
    int pp[2][2] = {{p0a, p1a}, {p0b, p1b}};
    #pragma unroll
    for (int mt = 0; mt < 2; mt++) {
        int row0 = bm + warpM * 32 + mt * 16 + gid;
        int row1 = row0 + 8;
        const float* pw0 = PWl + pp[mt][0] * 256;
        const float* pw1 = PWl + pp[mt][1] * 256;
        float s1r0 = 0.f, s2r0 = 0.f, s1r1 = 0.f, s2r1 = 0.f;
        #pragma unroll
        for (int nt = 0; nt < 8; nt++) {
            int col = bn + warpN * 64 + nt * 8 + tig * 2;
            float v00 = c[mt][nt][0] + pw0[col], v01 = c[mt][nt][1] + pw0[col + 1];
            float v10 = c[mt][nt][2] + pw1[col], v11 = c[mt][nt][3] + pw1[col + 1];
            s1r0 += v00 * lw[nt][0] + v01 * lw[nt][1];
            s2r0 += v00 * rw[nt][0] + v01 * rw[nt][1];
            s1r1 += v10 * lw[nt][0] + v11 * lw[nt][1];
            s2r1 += v10 * rw[nt][0] + v11 * rw[nt][1];
            if (row0 < NN)
                *(half2*)(g_ft + (size_t)row0 * FD + col) = __floats2half2_rn(v00, v01);
            if (row1 < NN)
                *(half2*)(g_ft + (size_t)row1 * FD + col) = __floats2half2_rn(v10, v11);
        }
        #pragma unroll
        for (int d = 1; d < 4; d <<= 1) {
            s1r0 += __shfl_xor_sync(0xffffffffu, s1r0, d);
            s2r0 += __shfl_xor_sync(0xffffffffu, s2r0, d);
            s1r1 += __shfl_xor_sync(0xffffffffu, s1r1, d);
            s2r1 += __shfl_xor_sync(0xffffffffu, s2r1, d);
        }
        if (tig == 0) {
            if (row0 < NN) { g_a1[row0 * 4 + h] = s1r0; g_a2[row0 * 4 + h] = s2r0; }
            if (row1 < NN) { g_a1[row1 * 4 + h] = s1r1; g_a2[row1 * 4 + h] = s2r1; }
        }
    }
}

// ---------------- edge phase: single-pass online softmax, fp16 gathers ----------------
__global__ void k_edge(float* __restrict__ out, int final_layer) {
    int gw = (blockIdx.x * blockDim.x + threadIdx.x) >> 5;
    int lane = threadIdx.x & 31;
    if (gw >= NN) return;
    int n = gw;
    int h = lane >> 3;
    float a2h = g_a2[n * 4 + h];
    int beg = g_off[n], end = g_off[n + 1];

    float m = -1e30f, ssum = 0.f;
    float acc[8] = {0, 0, 0, 0, 0, 0, 0, 0};

    if (beg < end) {
        int s = g_csr_src[beg];
        float a1v = g_a1[s * 4 + h];
        for (int i = beg; i < end; i++) {
            int s_nxt = 0; float a1_nxt = 0.f;
            if (i + 1 < end) {
                s_nxt = g_csr_src[i + 1];
                a1_nxt = g_a1[s_nxt * 4 + h];
            }
            float e = a1v + a2h;
            e = e > 0.f ? e : 0.2f * e;
            float mn = fmaxf(m, e);
            float sc = __expf(m - mn);
            float f = __expf(e - mn);
            ssum = ssum * sc + f;
            m = mn;
            uint4 q = *(const uint4*)(g_ft + (size_t)s * FD + lane * 8);
            float2 f0 = __half22float2(*(half2*)&q.x);
            float2 f1 = __half22float2(*(half2*)&q.y);
            float2 f2 = __half22float2(*(half2*)&q.z);
            float2 f3 = __half22float2(*(half2*)&q.w);
            acc[0] = acc[0] * sc + f0.x * f;  acc[1] = acc[1] * sc + f0.y * f;
            acc[2] = acc[2] * sc + f1.x * f;  acc[3] = acc[3] * sc + f1.y * f;
            acc[4] = acc[4] * sc + f2.x * f;  acc[5] = acc[5] * sc + f2.y * f;
            acc[6] = acc[6] * sc + f3.x * f;  acc[7] = acc[7] * sc + f3.y * f;
            s = s_nxt; a1v = a1_nxt;
        }
    }
    float inv = ssum > 0.f ? 1.0f / ssum : 0.f;
    #pragma unroll
    for (int j = 0; j < 8; j++) acc[j] *= inv;

    if (final_layer) {
        #pragma unroll
        for (int j = 0; j < 8; j++) {
            acc[j] += __shfl_xor_sync(0xffffffffu, acc[j], 8);
            acc[j] += __shfl_xor_sync(0xffffffffu, acc[j], 16);
        }
        if (lane < 8) {
            #pragma unroll
            for (int j = 0; j < 8; j++)
                out[n * 64 + lane * 8 + j] = acc[j] * 0.25f;
        }
        if (lane == 0) g_cnt[n] = 0;   // restore cnt==0 invariant for the next call
    } else {
        half2 h0 = __floats2half2_rn(acc[0] > 0.f ? acc[0] : expm1f(acc[0]),
                                     acc[1] > 0.f ? acc[1] : expm1f(acc[1]));
        half2 h1 = __floats2half2_rn(acc[2] > 0.f ? acc[2] : expm1f(acc[2]),
                                     acc[3] > 0.f ? acc[3] : expm1f(acc[3]));
        half2 h2 = __floats2half2_rn(acc[4] > 0.f ? acc[4] : expm1f(acc[4]),
                                     acc[5] > 0.f ? acc[5] : expm1f(acc[5]));
        half2 h3 = __floats2half2_rn(acc[6] > 0.f ? acc[6] : expm1f(acc[6]),
                                     acc[7] > 0.f ? acc[7] : expm1f(acc[7]));
        uint4 q;
        q.x = *(uint32_t*)&h0; q.y = *(uint32_t*)&h1;
        q.z = *(uint32_t*)&h2; q.w = *(uint32_t*)&h3;
        *(uint4*)(g_hcat + (size_t)n * HSTR + lane * 8) = q;
    }
}

// ---------------- launcher ----------------
extern "C" void kernel_launch(void* const* d_in, const int* in_sizes, int n_in,
                              void* d_out, int out_size) {
    const float* features = (const float*)d_in[0];
    const float* W0  = (const float*)d_in[1];
    const float* al0 = (const float*)d_in[2];
    const float* ar0 = (const float*)d_in[3];
    const float* pe0 = (const float*)d_in[4];
    const float* W1  = (const float*)d_in[5];
    const float* al1 = (const float*)d_in[6];
    const float* ar1 = (const float*)d_in[7];
    const float* pe1 = (const float*)d_in[8];
    const float* W2  = (const float*)d_in[9];
    const float* al2 = (const float*)d_in[10];
    const float* ar2 = (const float*)d_in[11];
    const float* pe2 = (const float*)d_in[12];
    const int* src = (const int*)d_in[13];
    const int* dst = (const int*)d_in[14];
    const int* pos = (const int*)d_in[15];
    float* out = (float*)d_out;

    __half* Wt0 = nullptr; cudaGetSymbolAddress((void**)&Wt0, g_WhT);
    __half* Wt1 = Wt0 + 256 * WK;
    __half* Wt2 = Wt0 + 2 * 256 * WK;
    float* PW0 = nullptr; cudaGetSymbolAddress((void**)&PW0, g_PW);
    float* PW1 = PW0 + 3 * 256;
    float* PW2 = PW0 + 2 * 3 * 256;

    cudaFuncSetAttribute(k_gemm_f16, cudaFuncAttributeMaxDynamicSharedMemorySize, GSMEM);

    dim3 ggrid(2, (NN + BM - 1) / BM);
    int edge_blocks = (NN + 7) / 8;

    // 9 launches total; GEMM stays the 4th (ncu capture lands on it).
    k_prep<<<PB_TOT, 256>>>(features, W0, W1, W2, pe0, pe1, pe2, dst);    // 1 (incl. count)
    k_scan<<<1, 1024>>>();                                                // 2
    k_place<<<(EE + 255) / 256, 256>>>(src, dst);                         // 3
    k_gemm_f16<<<ggrid, 256, GSMEM>>>(Wt0, 128, al0, ar0, PW0, pos);      // 4  <- profiled
    k_edge<<<edge_blocks, 256>>>(out, 0);                                 // 5
    k_gemm_f16<<<ggrid, 256, GSMEM>>>(Wt1, 256, al1, ar1, PW1, pos);      // 6
    k_edge<<<edge_blocks, 256>>>(out, 0);                                 // 7
    k_gemm_f16<<<ggrid, 256, GSMEM>>>(Wt2, 256, al2, ar2, PW2, pos);      // 8
    k_edge<<<edge_blocks, 256>>>(out, 1);                                 // 9
}